// round 1
// baseline (speedup 1.0000x reference)
#include <cuda_runtime.h>
#include <math.h>

// ---------------- scratch (static __device__ arrays; no allocations) ----------------
__device__ float g_pixel_space[8 * 256 * 4096];     //  33.5 MB
__device__ float g_pixel_kv  [8 * 384 * 4096];      //  50.3 MB
__device__ float g_query_space[8 * 256 * 128];
__device__ float g_query_qkv [8 * 512 * 128];
__device__ float g_sim       [8 * 8 * 128 * 4224];  // 138.4 MB
__device__ float g_ret       [8 * 256 * 128];
__device__ float g_qf        [8 * 256 * 128];
__device__ float g_ffn       [8 * 2048 * 128];

__device__ __forceinline__ float gelu_f(float x) {
    return 0.5f * x * (1.0f + erff(x * 0.70710678118654752440f));
}

// ---------------- generic SGEMM with folded-BN epilogue ----------------
// C[z] (M x Nn) = epilogue( A (M x K) @ B[z] (K x Nn) )
// epilogue: v = acc*sc[m] + bi[m]; (+res) ; (gelu)
// Requires: M % 128 == 0, Nn % 128 == 0, K % 16 == 0.
template <bool GELU_B, bool GELU_OUT, bool RES>
__global__ __launch_bounds__(256) void sgemm_bn_kernel(
    const float* __restrict__ A, const float* __restrict__ B, float* __restrict__ C,
    const float* __restrict__ sc, const float* __restrict__ bi,
    const float* __restrict__ res, int M, int Nn, int K)
{
    __shared__ float As[16][128];
    __shared__ float Bs[16][128];

    const int tid = threadIdx.x;
    const int bn = blockIdx.x, bm = blockIdx.y, z = blockIdx.z;
    const float* Bz = B + (size_t)z * K * Nn;

    float acc[8][8];
#pragma unroll
    for (int i = 0; i < 8; i++)
#pragma unroll
        for (int j = 0; j < 8; j++) acc[i][j] = 0.0f;

    const int tr = tid >> 4;   // 0..15
    const int tc = tid & 15;   // 0..15

    for (int k0 = 0; k0 < K; k0 += 16) {
        // A tile: 128 rows x 16 cols -> As[k][m]
#pragma unroll
        for (int it = 0; it < 2; it++) {
            int idx = tid + it * 256;
            int row = idx >> 2;
            int c4  = (idx & 3) << 2;
            float4 av = *reinterpret_cast<const float4*>(
                &A[(size_t)(bm * 128 + row) * K + k0 + c4]);
            As[c4 + 0][row] = av.x;
            As[c4 + 1][row] = av.y;
            As[c4 + 2][row] = av.z;
            As[c4 + 3][row] = av.w;
        }
        // B tile: 16 rows x 128 cols -> Bs[k][n]
#pragma unroll
        for (int it = 0; it < 2; it++) {
            int idx = tid + it * 256;
            int kr = idx >> 5;
            int c4 = (idx & 31) << 2;
            float4 bv = *reinterpret_cast<const float4*>(
                &Bz[(size_t)(k0 + kr) * Nn + bn * 128 + c4]);
            if (GELU_B) {
                bv.x = gelu_f(bv.x); bv.y = gelu_f(bv.y);
                bv.z = gelu_f(bv.z); bv.w = gelu_f(bv.w);
            }
            *reinterpret_cast<float4*>(&Bs[kr][c4]) = bv;
        }
        __syncthreads();

#pragma unroll
        for (int k = 0; k < 16; k++) {
            float a[8], b[8];
#pragma unroll
            for (int i = 0; i < 8; i++) a[i] = As[k][tr * 8 + i];
#pragma unroll
            for (int j = 0; j < 8; j++) b[j] = Bs[k][tc * 8 + j];
#pragma unroll
            for (int i = 0; i < 8; i++)
#pragma unroll
                for (int j = 0; j < 8; j++) acc[i][j] += a[i] * b[j];
        }
        __syncthreads();
    }

    float* Cz = C + (size_t)z * M * Nn;
    const float* Rz = RES ? (res + (size_t)z * M * Nn) : nullptr;
#pragma unroll
    for (int i = 0; i < 8; i++) {
        int gm = bm * 128 + tr * 8 + i;
        float s = sc[gm], bb = bi[gm];
#pragma unroll
        for (int j = 0; j < 8; j++) {
            int gn = bn * 128 + tc * 8 + j;
            float v = acc[i][j] * s + bb;
            if (RES) v += Rz[(size_t)gm * Nn + gn];
            if (GELU_OUT) v = gelu_f(v);
            Cz[(size_t)gm * Nn + gn] = v;
        }
    }
}

// ---------------- sim = scale_h * (q^T k_cat) + bias_h ----------------
// grid (33, 64): x = m-tile (128 wide, 4224 total), y = n*8+h
__global__ __launch_bounds__(256) void sim_kernel(
    const float* __restrict__ qkv,   // (8,512,128)
    const float* __restrict__ pkv,   // (8,384,4096)
    const float* __restrict__ s_sim, const float* __restrict__ b_sim,
    float* __restrict__ sim)         // (64,128,4224)
{
    __shared__ float qs[16][128];
    __shared__ float ks[16][128];

    const int nh = blockIdx.y, n = nh >> 3, h = nh & 7;
    const int m0 = blockIdx.x * 128;
    const int tid = threadIdx.x;

    const float* qb = qkv + ((size_t)n * 512 + h * 16) * 128;
#pragma unroll
    for (int it = 0; it < 8; it++) {
        int idx = tid + it * 256;
        int d = idx >> 7, l = idx & 127;
        qs[d][l] = qb[d * 128 + l];
    }
#pragma unroll
    for (int it = 0; it < 8; it++) {
        int idx = tid + it * 256;
        int d = idx >> 7, mm = idx & 127;
        int m = m0 + mm;
        float v;
        if (m < 128)
            v = qkv[((size_t)n * 512 + 128 + h * 16 + d) * 128 + m];
        else
            v = pkv[((size_t)n * 384 + h * 16 + d) * 4096 + (m - 128)];
        ks[d][mm] = v;
    }
    __syncthreads();

    const int tr = tid >> 4, tc = tid & 15;
    float acc[8][8];
#pragma unroll
    for (int i = 0; i < 8; i++)
#pragma unroll
        for (int j = 0; j < 8; j++) acc[i][j] = 0.0f;

#pragma unroll
    for (int d = 0; d < 16; d++) {
        float a[8], b[8];
#pragma unroll
        for (int i = 0; i < 8; i++) a[i] = qs[d][tr * 8 + i];
#pragma unroll
        for (int j = 0; j < 8; j++) b[j] = ks[d][tc * 8 + j];
#pragma unroll
        for (int i = 0; i < 8; i++)
#pragma unroll
            for (int j = 0; j < 8; j++) acc[i][j] += a[i] * b[j];
    }

    const float ss = s_sim[h], sb = b_sim[h];
    float* out = sim + (size_t)nh * 128 * 4224;
#pragma unroll
    for (int i = 0; i < 8; i++) {
        int l = tr * 8 + i;
#pragma unroll
        for (int j = 0; j < 8; j++) {
            int m = m0 + tc * 8 + j;
            out[(size_t)l * 4224 + m] = acc[i][j] * ss + sb;
        }
    }
}

// ---------------- softmax over rows of length 4224 (in place) ----------------
__global__ __launch_bounds__(256) void softmax_kernel(float* __restrict__ sim)
{
    const int ROWLEN = 4224;
    float* p = sim + (size_t)blockIdx.x * ROWLEN;
    const int tid = threadIdx.x;
    __shared__ float smax[8];
    __shared__ float ssum[8];

    float m = -3.4e38f;
    for (int i = tid; i < ROWLEN; i += 256) m = fmaxf(m, p[i]);
#pragma unroll
    for (int o = 16; o > 0; o >>= 1) m = fmaxf(m, __shfl_xor_sync(0xffffffffu, m, o));
    if ((tid & 31) == 0) smax[tid >> 5] = m;
    __syncthreads();
    float mall = fmaxf(fmaxf(fmaxf(smax[0], smax[1]), fmaxf(smax[2], smax[3])),
                       fmaxf(fmaxf(smax[4], smax[5]), fmaxf(smax[6], smax[7])));

    float s = 0.0f;
    for (int i = tid; i < ROWLEN; i += 256) s += expf(p[i] - mall);
#pragma unroll
    for (int o = 16; o > 0; o >>= 1) s += __shfl_xor_sync(0xffffffffu, s, o);
    if ((tid & 31) == 0) ssum[tid >> 5] = s;
    __syncthreads();
    float tot = ssum[0] + ssum[1] + ssum[2] + ssum[3] +
                ssum[4] + ssum[5] + ssum[6] + ssum[7];
    float inv = 1.0f / tot;
    for (int i = tid; i < ROWLEN; i += 256) p[i] = expf(p[i] - mall) * inv;
}

// ---------------- ret = gelu(bn(attn @ v_cat^T)) ----------------
// grid (64, 2): x = n*8+h, y = l-half (64 queries each). No split-K => deterministic.
__global__ __launch_bounds__(256) void ret_kernel(
    const float* __restrict__ qkv,   // (8,512,128)
    const float* __restrict__ pkv,   // (8,384,4096)
    const float* __restrict__ attn,  // (64,128,4224) normalized
    const float* __restrict__ s_ret, const float* __restrict__ b_ret,
    float* __restrict__ ret)         // (8,256,128)
{
    __shared__ float vs[32][128];

    const int nh = blockIdx.x, n = nh >> 3, h = nh & 7;
    const int lt = blockIdx.y;
    const int tid = threadIdx.x;
    const int l = lt * 64 + (tid & 63);
    const int dq = tid >> 6;          // 0..3 -> owns d in [dq*8, dq*8+8)

    float acc[8];
#pragma unroll
    for (int d = 0; d < 8; d++) acc[d] = 0.0f;

    const float* arow = attn + ((size_t)nh * 128 + l) * 4224;

    for (int c = 0; c < 33; c++) {
        int m0 = c * 128;
#pragma unroll
        for (int it = 0; it < 16; it++) {
            int idx = tid + it * 256;
            int d = idx >> 7, mm = idx & 127;
            int m = m0 + mm;
            float v;
            if (m < 128)
                v = qkv[((size_t)n * 512 + 256 + h * 32 + d) * 128 + m];
            else
                v = pkv[((size_t)n * 384 + 128 + h * 32 + d) * 4096 + (m - 128)];
            vs[d][mm] = v;
        }
        __syncthreads();

#pragma unroll 4
        for (int mm = 0; mm < 128; mm++) {
            float pv = arow[m0 + mm];
#pragma unroll
            for (int d = 0; d < 8; d++) acc[d] += pv * vs[dq * 8 + d][mm];
        }
        __syncthreads();
    }

#pragma unroll
    for (int d = 0; d < 8; d++) {
        int ch = h * 32 + dq * 8 + d;
        float v = acc[d] * s_ret[ch] + b_ret[ch];
        ret[((size_t)n * 256 + ch) * 128 + l] = gelu_f(v);
    }
}

// ---------------- host ----------------
extern "C" void kernel_launch(void* const* d_in, const int* in_sizes, int n_in,
                              void* d_out, int out_size)
{
    (void)in_sizes; (void)n_in; (void)out_size;

    const float* pixel = (const float*)d_in[0];
    const float* query = (const float*)d_in[1];
    const float* w_q1  = (const float*)d_in[2];
    const float* s_q1  = (const float*)d_in[3];
    const float* b_q1  = (const float*)d_in[4];
    const float* w_p1  = (const float*)d_in[5];
    const float* s_p1  = (const float*)d_in[6];
    const float* b_p1  = (const float*)d_in[7];
    const float* w_qkv = (const float*)d_in[8];
    const float* s_qkv = (const float*)d_in[9];
    const float* b_qkv = (const float*)d_in[10];
    const float* w_pkv = (const float*)d_in[11];
    const float* s_pkv = (const float*)d_in[12];
    const float* b_pkv = (const float*)d_in[13];
    const float* s_sim = (const float*)d_in[14];
    const float* b_sim = (const float*)d_in[15];
    const float* s_ret = (const float*)d_in[16];
    const float* b_ret = (const float*)d_in[17];
    const float* w_c3  = (const float*)d_in[18];
    const float* s_c3  = (const float*)d_in[19];
    const float* b_c3  = (const float*)d_in[20];
    const float* w_f1  = (const float*)d_in[21];
    const float* s_f1  = (const float*)d_in[22];
    const float* b_f1  = (const float*)d_in[23];
    const float* w_f2  = (const float*)d_in[24];
    const float* s_f2  = (const float*)d_in[25];
    const float* b_f2  = (const float*)d_in[26];
    float* out = (float*)d_out;

    float *ps, *pkvp, *qs, *qqkv, *simp, *retp, *qfp, *ffnp;
    cudaGetSymbolAddress((void**)&ps,   g_pixel_space);
    cudaGetSymbolAddress((void**)&pkvp, g_pixel_kv);
    cudaGetSymbolAddress((void**)&qs,   g_query_space);
    cudaGetSymbolAddress((void**)&qqkv, g_query_qkv);
    cudaGetSymbolAddress((void**)&simp, g_sim);
    cudaGetSymbolAddress((void**)&retp, g_ret);
    cudaGetSymbolAddress((void**)&qfp,  g_qf);
    cudaGetSymbolAddress((void**)&ffnp, g_ffn);

    // 1) pixel_space = gelu(bn(w_p1 @ gelu(pixel)))   M=256 K=2048 N=4096 x8
    sgemm_bn_kernel<true, true, false><<<dim3(32, 2, 8), 256>>>(
        w_p1, pixel, ps, s_p1, b_p1, nullptr, 256, 4096, 2048);
    // 2) query_space = gelu(bn(w_q1 @ query))         M=256 K=256 N=128 x8
    sgemm_bn_kernel<false, true, false><<<dim3(1, 2, 8), 256>>>(
        w_q1, query, qs, s_q1, b_q1, nullptr, 256, 128, 256);
    // 3) pixel_kv = bn(w_pkv @ pixel_space)           M=384 K=256 N=4096 x8
    sgemm_bn_kernel<false, false, false><<<dim3(32, 3, 8), 256>>>(
        w_pkv, ps, pkvp, s_pkv, b_pkv, nullptr, 384, 4096, 256);
    // 4) query_qkv = bn(w_qkv @ query_space)          M=512 K=256 N=128 x8
    sgemm_bn_kernel<false, false, false><<<dim3(1, 4, 8), 256>>>(
        w_qkv, qs, qqkv, s_qkv, b_qkv, nullptr, 512, 128, 256);
    // 5) sim + per-head scale/bias
    sim_kernel<<<dim3(33, 64), 256>>>(qqkv, pkvp, s_sim, b_sim, simp);
    // 6) softmax rows
    softmax_kernel<<<8192, 256>>>(simp);
    // 7) ret = gelu(bn(attn @ v^T))
    ret_kernel<<<dim3(64, 2), 256>>>(qqkv, pkvp, simp, s_ret, b_ret, retp);
    // 8) qf = gelu(query + bn(w_c3 @ ret))            M=256 K=256 N=128 x8
    sgemm_bn_kernel<false, true, true><<<dim3(1, 2, 8), 256>>>(
        w_c3, retp, qfp, s_c3, b_c3, query, 256, 128, 256);
    // 9) ffn = gelu(bn(w_f1 @ qf))                    M=2048 K=256 N=128 x8
    sgemm_bn_kernel<false, true, false><<<dim3(1, 16, 8), 256>>>(
        w_f1, qfp, ffnp, s_f1, b_f1, nullptr, 2048, 128, 256);
    // 10) out = gelu(qf + bn(w_f2 @ ffn))             M=256 K=2048 N=128 x8
    sgemm_bn_kernel<false, true, true><<<dim3(1, 2, 8), 256>>>(
        w_f2, ffnp, out, s_f2, b_f2, qfp, 256, 128, 2048);
}

// round 7
// speedup vs baseline: 1.3565x; 1.3565x over previous
#include <cuda_runtime.h>
#include <cuda_bf16.h>
#include <math.h>
#include <stdint.h>

// ---------------- scratch (static __device__ arrays; no allocations) ----------------
__device__ float g_pixel_space[8 * 256 * 4096];
__device__ float g_pixel_kv  [8 * 384 * 4096];
__device__ float g_query_space[8 * 256 * 128];
__device__ float g_query_qkv [8 * 512 * 128];
__device__ float g_sim       [8 * 8 * 128 * 4224];
__device__ float g_ret       [8 * 256 * 128];
__device__ float g_qf        [8 * 256 * 128];
__device__ float g_ffn       [8 * 2048 * 128];

// ---------------- fast exact-gelu (A&S 7.1.26 erf, |err_erf| < 1.5e-7) ----------------
__device__ __forceinline__ float gelu_f(float x) {
    float ax = fabsf(x) * 0.70710678118654752440f;
    float t = __fdividef(1.0f, fmaf(0.3275911f, ax, 1.0f));
    float y = t * fmaf(t, fmaf(t, fmaf(t, fmaf(t, 1.061405429f, -1.453152027f),
                                       1.421413741f), -0.284496736f), 0.254829592f);
    float e = __expf(-ax * ax);
    float er = 1.0f - y * e;
    er = copysignf(er, x);
    return 0.5f * x * (1.0f + er);
}

// split x,y into packed bf16 hi and lo words
__device__ __forceinline__ void split_pack(float x, float y, uint32_t& h, uint32_t& l) {
    __nv_bfloat16 hx = __float2bfloat16_rn(x);
    __nv_bfloat16 hy = __float2bfloat16_rn(y);
    __nv_bfloat16 lx = __float2bfloat16_rn(x - __bfloat162float(hx));
    __nv_bfloat16 ly = __float2bfloat16_rn(y - __bfloat162float(hy));
    h = ((uint32_t)__bfloat16_as_ushort(hy) << 16) | __bfloat16_as_ushort(hx);
    l = ((uint32_t)__bfloat16_as_ushort(ly) << 16) | __bfloat16_as_ushort(lx);
}

// baseline-PTX tensor op: m16n8k16 row.col f32 += bf16*bf16
__device__ __forceinline__ void mma_bf16(float* d, const uint32_t* a, const uint32_t* b) {
    asm volatile(
        "mma.sync.aligned.m16n8k16.row.col.f32.bf16.bf16.f32 "
        "{%0,%1,%2,%3}, {%4,%5,%6,%7}, {%8,%9}, {%0,%1,%2,%3};"
        : "+f"(d[0]), "+f"(d[1]), "+f"(d[2]), "+f"(d[3])
        : "r"(a[0]), "r"(a[1]), "r"(a[2]), "r"(a[3]), "r"(b[0]), "r"(b[1]));
}

// ---------------- split-bf16 tensor GEMM (mma.sync; compute_103-safe) ----------------
// C[z](M x Nn) = epi( A(M x K) @ B[z](K x Nn) ); block tile 128x128, BK=32.
// 8 warps = 2(m) x 4(n); warp tile 64x32; 3 MMAs (hh+hl+lh) per fragment pair.
#define SMEM_LD 36  // row stride in bf16 elems (32 + 4 pad)

template <bool GELU_B, bool GELU_OUT, bool RES>
__global__ __launch_bounds__(256) void mma_gemm(
    const float* __restrict__ A, const float* __restrict__ B, float* __restrict__ C,
    const float* __restrict__ sc, const float* __restrict__ bi,
    const float* __restrict__ res, int M, int Nn, int K)
{
    __shared__ uint16_t Ah[128][SMEM_LD], Al[128][SMEM_LD];
    __shared__ uint16_t Bh[128][SMEM_LD], Bl[128][SMEM_LD];

    const int tid = threadIdx.x;
    const int lane = tid & 31, warp = tid >> 5;
    const int wm = warp >> 2, wn = warp & 3;
    const int m0 = blockIdx.x * 128, n0 = blockIdx.y * 128, z = blockIdx.z;
    const float* Bz = B + (size_t)z * K * Nn;

    float acc[4][4][4];
#pragma unroll
    for (int mi = 0; mi < 4; mi++)
#pragma unroll
        for (int ni = 0; ni < 4; ni++)
#pragma unroll
            for (int q = 0; q < 4; q++) acc[mi][ni][q] = 0.0f;

    // staging registers
    float4 pa[4];
    float pb[4][4];
    const int bncol = tid & 127;
    const int bkhalf = (tid >> 7) * 4;
    const int NC = K >> 5;

    // prefetch chunk 0
#pragma unroll
    for (int it = 0; it < 4; it++) {
        int lin = tid + it * 256;
        int row = lin >> 3, c4 = (lin & 7) << 2;
        pa[it] = *reinterpret_cast<const float4*>(&A[(size_t)(m0 + row) * K + c4]);
    }
#pragma unroll
    for (int it = 0; it < 4; it++)
#pragma unroll
        for (int j = 0; j < 4; j++) {
            int k = bkhalf + it * 8 + j;
            pb[it][j] = Bz[(size_t)k * Nn + n0 + bncol];
        }

    for (int kc = 0; kc < NC; kc++) {
        // convert + store staged chunk
#pragma unroll
        for (int it = 0; it < 4; it++) {
            int lin = tid + it * 256;
            int row = lin >> 3, c4 = (lin & 7) << 2;
            float4 v = pa[it];
            uint32_t h0, l0, h1, l1;
            split_pack(v.x, v.y, h0, l0);
            split_pack(v.z, v.w, h1, l1);
            *reinterpret_cast<uint32_t*>(&Ah[row][c4])     = h0;
            *reinterpret_cast<uint32_t*>(&Al[row][c4])     = l0;
            *reinterpret_cast<uint32_t*>(&Ah[row][c4 + 2]) = h1;
            *reinterpret_cast<uint32_t*>(&Al[row][c4 + 2]) = l1;
        }
#pragma unroll
        for (int it = 0; it < 4; it++) {
            float x0 = pb[it][0], x1 = pb[it][1], x2 = pb[it][2], x3 = pb[it][3];
            if (GELU_B) { x0 = gelu_f(x0); x1 = gelu_f(x1); x2 = gelu_f(x2); x3 = gelu_f(x3); }
            uint32_t h0, l0, h1, l1;
            split_pack(x0, x1, h0, l0);
            split_pack(x2, x3, h1, l1);
            int kb = bkhalf + it * 8;
            *reinterpret_cast<uint32_t*>(&Bh[bncol][kb])     = h0;
            *reinterpret_cast<uint32_t*>(&Bl[bncol][kb])     = l0;
            *reinterpret_cast<uint32_t*>(&Bh[bncol][kb + 2]) = h1;
            *reinterpret_cast<uint32_t*>(&Bl[bncol][kb + 2]) = l1;
        }
        __syncthreads();

        // prefetch next chunk (LDG latency hidden by compute below)
        if (kc + 1 < NC) {
            int ko = (kc + 1) * 32;
#pragma unroll
            for (int it = 0; it < 4; it++) {
                int lin = tid + it * 256;
                int row = lin >> 3, c4 = (lin & 7) << 2;
                pa[it] = *reinterpret_cast<const float4*>(&A[(size_t)(m0 + row) * K + ko + c4]);
            }
#pragma unroll
            for (int it = 0; it < 4; it++)
#pragma unroll
                for (int j = 0; j < 4; j++) {
                    int k = ko + bkhalf + it * 8 + j;
                    pb[it][j] = Bz[(size_t)k * Nn + n0 + bncol];
                }
        }

        // compute: 2 k-steps of 16
#pragma unroll
        for (int ks = 0; ks < 2; ks++) {
            const int kf = ks * 16 + (lane & 3) * 2;
            uint32_t bh[4][2], bl[4][2];
#pragma unroll
            for (int ni = 0; ni < 4; ni++) {
                int n = wn * 32 + ni * 8 + (lane >> 2);
                bh[ni][0] = *reinterpret_cast<const uint32_t*>(&Bh[n][kf]);
                bh[ni][1] = *reinterpret_cast<const uint32_t*>(&Bh[n][kf + 8]);
                bl[ni][0] = *reinterpret_cast<const uint32_t*>(&Bl[n][kf]);
                bl[ni][1] = *reinterpret_cast<const uint32_t*>(&Bl[n][kf + 8]);
            }
#pragma unroll
            for (int mi = 0; mi < 4; mi++) {
                int r = wm * 64 + mi * 16 + (lane >> 2);
                uint32_t ah[4], al[4];
                ah[0] = *reinterpret_cast<const uint32_t*>(&Ah[r][kf]);
                ah[1] = *reinterpret_cast<const uint32_t*>(&Ah[r + 8][kf]);
                ah[2] = *reinterpret_cast<const uint32_t*>(&Ah[r][kf + 8]);
                ah[3] = *reinterpret_cast<const uint32_t*>(&Ah[r + 8][kf + 8]);
                al[0] = *reinterpret_cast<const uint32_t*>(&Al[r][kf]);
                al[1] = *reinterpret_cast<const uint32_t*>(&Al[r + 8][kf]);
                al[2] = *reinterpret_cast<const uint32_t*>(&Al[r][kf + 8]);
                al[3] = *reinterpret_cast<const uint32_t*>(&Al[r + 8][kf + 8]);
#pragma unroll
                for (int ni = 0; ni < 4; ni++) {
                    mma_bf16(acc[mi][ni], ah, bh[ni]);
                    mma_bf16(acc[mi][ni], ah, bl[ni]);
                    mma_bf16(acc[mi][ni], al, bh[ni]);
                }
            }
        }
        __syncthreads();
    }

    // ---------------- epilogue ----------------
    float* Cz = C + (size_t)z * M * Nn;
    const float* Rz = RES ? (res + (size_t)z * M * Nn) : nullptr;
#pragma unroll
    for (int mi = 0; mi < 4; mi++) {
        int r0 = m0 + wm * 64 + mi * 16 + (lane >> 2);
        int r1 = r0 + 8;
        float s0 = sc[r0], bb0 = bi[r0];
        float s1 = sc[r1], bb1 = bi[r1];
#pragma unroll
        for (int ni = 0; ni < 4; ni++) {
            int c = n0 + wn * 32 + ni * 8 + (lane & 3) * 2;
            float2 v0, v1;
            v0.x = acc[mi][ni][0] * s0 + bb0;
            v0.y = acc[mi][ni][1] * s0 + bb0;
            v1.x = acc[mi][ni][2] * s1 + bb1;
            v1.y = acc[mi][ni][3] * s1 + bb1;
            if (RES) {
                float2 rr0 = *reinterpret_cast<const float2*>(&Rz[(size_t)r0 * Nn + c]);
                float2 rr1 = *reinterpret_cast<const float2*>(&Rz[(size_t)r1 * Nn + c]);
                v0.x += rr0.x; v0.y += rr0.y;
                v1.x += rr1.x; v1.y += rr1.y;
            }
            if (GELU_OUT) {
                v0.x = gelu_f(v0.x); v0.y = gelu_f(v0.y);
                v1.x = gelu_f(v1.x); v1.y = gelu_f(v1.y);
            }
            *reinterpret_cast<float2*>(&Cz[(size_t)r0 * Nn + c]) = v0;
            *reinterpret_cast<float2*>(&Cz[(size_t)r1 * Nn + c]) = v1;
        }
    }
}

// ---------------- sim = scale_h * (q^T k_cat) + bias_h ----------------
__global__ __launch_bounds__(256) void sim_kernel(
    const float* __restrict__ qkv, const float* __restrict__ pkv,
    const float* __restrict__ s_sim, const float* __restrict__ b_sim,
    float* __restrict__ sim)
{
    __shared__ float qs[16][128];
    __shared__ float ks[16][128];

    const int nh = blockIdx.y, n = nh >> 3, h = nh & 7;
    const int m0 = blockIdx.x * 128;
    const int tid = threadIdx.x;

    const float* qb = qkv + ((size_t)n * 512 + h * 16) * 128;
#pragma unroll
    for (int it = 0; it < 8; it++) {
        int idx = tid + it * 256;
        int d = idx >> 7, l = idx & 127;
        qs[d][l] = qb[d * 128 + l];
    }
#pragma unroll
    for (int it = 0; it < 8; it++) {
        int idx = tid + it * 256;
        int d = idx >> 7, mm = idx & 127;
        int m = m0 + mm;
        float v;
        if (m < 128)
            v = qkv[((size_t)n * 512 + 128 + h * 16 + d) * 128 + m];
        else
            v = pkv[((size_t)n * 384 + h * 16 + d) * 4096 + (m - 128)];
        ks[d][mm] = v;
    }
    __syncthreads();

    const int tr = tid >> 4, tc = tid & 15;
    float acc[8][8];
#pragma unroll
    for (int i = 0; i < 8; i++)
#pragma unroll
        for (int j = 0; j < 8; j++) acc[i][j] = 0.0f;

#pragma unroll
    for (int d = 0; d < 16; d++) {
        float a[8], b[8];
#pragma unroll
        for (int i = 0; i < 8; i++) a[i] = qs[d][tr * 8 + i];
#pragma unroll
        for (int j = 0; j < 8; j++) b[j] = ks[d][tc * 8 + j];
#pragma unroll
        for (int i = 0; i < 8; i++)
#pragma unroll
            for (int j = 0; j < 8; j++) acc[i][j] += a[i] * b[j];
    }

    const float ss = s_sim[h], sbv = b_sim[h];
    float* out = sim + (size_t)nh * 128 * 4224;
#pragma unroll
    for (int i = 0; i < 8; i++) {
        int l = tr * 8 + i;
#pragma unroll
        for (int j = 0; j < 8; j++) {
            int m = m0 + tc * 8 + j;
            out[(size_t)l * 4224 + m] = acc[i][j] * ss + sbv;
        }
    }
}

// ---------------- softmax over rows of length 4224 (in place) ----------------
__global__ __launch_bounds__(256) void softmax_kernel(float* __restrict__ sim)
{
    const int ROWLEN = 4224;
    float* p = sim + (size_t)blockIdx.x * ROWLEN;
    const int tid = threadIdx.x;
    __shared__ float smax[8];
    __shared__ float ssum[8];

    float m = -3.4e38f;
    for (int i = tid; i < ROWLEN; i += 256) m = fmaxf(m, p[i]);
#pragma unroll
    for (int o = 16; o > 0; o >>= 1) m = fmaxf(m, __shfl_xor_sync(0xffffffffu, m, o));
    if ((tid & 31) == 0) smax[tid >> 5] = m;
    __syncthreads();
    float mall = fmaxf(fmaxf(fmaxf(smax[0], smax[1]), fmaxf(smax[2], smax[3])),
                       fmaxf(fmaxf(smax[4], smax[5]), fmaxf(smax[6], smax[7])));

    float s = 0.0f;
    for (int i = tid; i < ROWLEN; i += 256) {
        float e = __expf(p[i] - mall);
        p[i] = e;
        s += e;
    }
#pragma unroll
    for (int o = 16; o > 0; o >>= 1) s += __shfl_xor_sync(0xffffffffu, s, o);
    if ((tid & 31) == 0) ssum[tid >> 5] = s;
    __syncthreads();
    float tot = ssum[0] + ssum[1] + ssum[2] + ssum[3] +
                ssum[4] + ssum[5] + ssum[6] + ssum[7];
    float inv = 1.0f / tot;
    for (int i = tid; i < ROWLEN; i += 256) p[i] *= inv;
}

// ---------------- ret = gelu(bn(attn @ v_cat^T)) ----------------
__global__ __launch_bounds__(256) void ret_kernel(
    const float* __restrict__ qkv, const float* __restrict__ pkv,
    const float* __restrict__ attn,
    const float* __restrict__ s_ret, const float* __restrict__ b_ret,
    float* __restrict__ ret)
{
    __shared__ float vs[32][128];

    const int nh = blockIdx.x, n = nh >> 3, h = nh & 7;
    const int lt = blockIdx.y;
    const int tid = threadIdx.x;
    const int l = lt * 64 + (tid & 63);
    const int dq = tid >> 6;

    float acc[8];
#pragma unroll
    for (int d = 0; d < 8; d++) acc[d] = 0.0f;

    const float* arow = attn + ((size_t)nh * 128 + l) * 4224;

    for (int c = 0; c < 33; c++) {
        int m0 = c * 128;
#pragma unroll
        for (int it = 0; it < 16; it++) {
            int idx = tid + it * 256;
            int d = idx >> 7, mm = idx & 127;
            int m = m0 + mm;
            float v;
            if (m < 128)
                v = qkv[((size_t)n * 512 + 256 + h * 32 + d) * 128 + m];
            else
                v = pkv[((size_t)n * 384 + 128 + h * 32 + d) * 4096 + (m - 128)];
            vs[d][mm] = v;
        }
        __syncthreads();

#pragma unroll 4
        for (int mm = 0; mm < 128; mm++) {
            float pv = arow[m0 + mm];
#pragma unroll
            for (int d = 0; d < 8; d++) acc[d] += pv * vs[dq * 8 + d][mm];
        }
        __syncthreads();
    }

#pragma unroll
    for (int d = 0; d < 8; d++) {
        int ch = h * 32 + dq * 8 + d;
        float v = acc[d] * s_ret[ch] + b_ret[ch];
        ret[((size_t)n * 256 + ch) * 128 + l] = gelu_f(v);
    }
}

// ---------------- host ----------------
extern "C" void kernel_launch(void* const* d_in, const int* in_sizes, int n_in,
                              void* d_out, int out_size)
{
    (void)in_sizes; (void)n_in; (void)out_size;

    const float* pixel = (const float*)d_in[0];
    const float* query = (const float*)d_in[1];
    const float* w_q1  = (const float*)d_in[2];
    const float* s_q1  = (const float*)d_in[3];
    const float* b_q1  = (const float*)d_in[4];
    const float* w_p1  = (const float*)d_in[5];
    const float* s_p1  = (const float*)d_in[6];
    const float* b_p1  = (const float*)d_in[7];
    const float* w_qkv = (const float*)d_in[8];
    const float* s_qkv = (const float*)d_in[9];
    const float* b_qkv = (const float*)d_in[10];
    const float* w_pkv = (const float*)d_in[11];
    const float* s_pkv = (const float*)d_in[12];
    const float* b_pkv = (const float*)d_in[13];
    const float* s_sim = (const float*)d_in[14];
    const float* b_sim = (const float*)d_in[15];
    const float* s_ret = (const float*)d_in[16];
    const float* b_ret = (const float*)d_in[17];
    const float* w_c3  = (const float*)d_in[18];
    const float* s_c3  = (const float*)d_in[19];
    const float* b_c3  = (const float*)d_in[20];
    const float* w_f1  = (const float*)d_in[21];
    const float* s_f1  = (const float*)d_in[22];
    const float* b_f1  = (const float*)d_in[23];
    const float* w_f2  = (const float*)d_in[24];
    const float* s_f2  = (const float*)d_in[25];
    const float* b_f2  = (const float*)d_in[26];
    float* out = (float*)d_out;

    float *ps, *pkvp, *qs, *qqkv, *simp, *retp, *qfp, *ffnp;
    cudaGetSymbolAddress((void**)&ps,   g_pixel_space);
    cudaGetSymbolAddress((void**)&pkvp, g_pixel_kv);
    cudaGetSymbolAddress((void**)&qs,   g_query_space);
    cudaGetSymbolAddress((void**)&qqkv, g_query_qkv);
    cudaGetSymbolAddress((void**)&simp, g_sim);
    cudaGetSymbolAddress((void**)&retp, g_ret);
    cudaGetSymbolAddress((void**)&qfp,  g_qf);
    cudaGetSymbolAddress((void**)&ffnp, g_ffn);

    // 1) pixel_space = gelu(bn(w_p1 @ gelu(pixel)))   M=256 K=2048 N=4096 x8
    mma_gemm<true, true, false><<<dim3(2, 32, 8), 256>>>(
        w_p1, pixel, ps, s_p1, b_p1, nullptr, 256, 4096, 2048);
    // 2) query_space = gelu(bn(w_q1 @ query))         M=256 K=256 N=128 x8
    mma_gemm<false, true, false><<<dim3(2, 1, 8), 256>>>(
        w_q1, query, qs, s_q1, b_q1, nullptr, 256, 128, 256);
    // 3) pixel_kv = bn(w_pkv @ pixel_space)           M=384 K=256 N=4096 x8
    mma_gemm<false, false, false><<<dim3(3, 32, 8), 256>>>(
        w_pkv, ps, pkvp, s_pkv, b_pkv, nullptr, 384, 4096, 256);
    // 4) query_qkv = bn(w_qkv @ query_space)          M=512 K=256 N=128 x8
    mma_gemm<false, false, false><<<dim3(4, 1, 8), 256>>>(
        w_qkv, qs, qqkv, s_qkv, b_qkv, nullptr, 512, 128, 256);
    // 5) sim + per-head scale/bias
    sim_kernel<<<dim3(33, 64), 256>>>(qqkv, pkvp, s_sim, b_sim, simp);
    // 6) softmax rows
    softmax_kernel<<<8192, 256>>>(simp);
    // 7) ret = gelu(bn(attn @ v^T))
    ret_kernel<<<dim3(64, 2), 256>>>(qqkv, pkvp, simp, s_ret, b_ret, retp);
    // 8) qf = gelu(query + bn(w_c3 @ ret))            M=256 K=256 N=128 x8
    mma_gemm<false, true, true><<<dim3(2, 1, 8), 256>>>(
        w_c3, retp, qfp, s_c3, b_c3, query, 256, 128, 256);
    // 9) ffn = gelu(bn(w_f1 @ qf))                    M=2048 K=256 N=128 x8
    mma_gemm<false, true, false><<<dim3(16, 1, 8), 256>>>(
        w_f1, qfp, ffnp, s_f1, b_f1, nullptr, 2048, 128, 256);
    // 10) out = gelu(qf + bn(w_f2 @ ffn))             M=256 K=2048 N=128 x8
    mma_gemm<false, true, true><<<dim3(2, 1, 8), 256>>>(
        w_f2, ffnp, out, s_f2, b_f2, qfp, 256, 128, 2048);
}

// round 9
// speedup vs baseline: 2.4786x; 1.8272x over previous
#include <cuda_runtime.h>
#include <cuda_bf16.h>
#include <math.h>
#include <stdint.h>

// ---------------- scratch (static __device__ arrays; no allocations) ----------------
__device__ float g_pixel_space[8 * 256 * 4096];
__device__ float g_pixel_kv  [8 * 384 * 4096];
__device__ float g_query_space[8 * 256 * 128];
__device__ float g_query_qkv [8 * 512 * 128];
__device__ float g_ret       [8 * 256 * 128];
__device__ float g_qf        [8 * 256 * 128];
__device__ float g_ffn       [8 * 2048 * 128];

// ---------------- fast exact-gelu (A&S 7.1.26 erf, |err_erf| < 1.5e-7) ----------------
__device__ __forceinline__ float gelu_f(float x) {
    float ax = fabsf(x) * 0.70710678118654752440f;
    float t = __fdividef(1.0f, fmaf(0.3275911f, ax, 1.0f));
    float y = t * fmaf(t, fmaf(t, fmaf(t, fmaf(t, 1.061405429f, -1.453152027f),
                                       1.421413741f), -0.284496736f), 0.254829592f);
    float e = __expf(-ax * ax);
    float er = 1.0f - y * e;
    er = copysignf(er, x);
    return 0.5f * x * (1.0f + er);
}

// split x,y into packed bf16 hi and lo words
__device__ __forceinline__ void split_pack(float x, float y, uint32_t& h, uint32_t& l) {
    __nv_bfloat16 hx = __float2bfloat16_rn(x);
    __nv_bfloat16 hy = __float2bfloat16_rn(y);
    __nv_bfloat16 lx = __float2bfloat16_rn(x - __bfloat162float(hx));
    __nv_bfloat16 ly = __float2bfloat16_rn(y - __bfloat162float(hy));
    h = ((uint32_t)__bfloat16_as_ushort(hy) << 16) | __bfloat16_as_ushort(hx);
    l = ((uint32_t)__bfloat16_as_ushort(ly) << 16) | __bfloat16_as_ushort(lx);
}

__device__ __forceinline__ void split_u16(float x, uint16_t& h, uint16_t& l) {
    __nv_bfloat16 hx = __float2bfloat16_rn(x);
    __nv_bfloat16 lx = __float2bfloat16_rn(x - __bfloat162float(hx));
    h = __bfloat16_as_ushort(hx);
    l = __bfloat16_as_ushort(lx);
}

// baseline-PTX tensor op: m16n8k16 row.col f32 += bf16*bf16
__device__ __forceinline__ void mma_bf16(float* d, const uint32_t* a, const uint32_t* b) {
    asm volatile(
        "mma.sync.aligned.m16n8k16.row.col.f32.bf16.bf16.f32 "
        "{%0,%1,%2,%3}, {%4,%5,%6,%7}, {%8,%9}, {%0,%1,%2,%3};"
        : "+f"(d[0]), "+f"(d[1]), "+f"(d[2]), "+f"(d[3])
        : "r"(a[0]), "r"(a[1]), "r"(a[2]), "r"(a[3]), "r"(b[0]), "r"(b[1]));
}

// ---------------- split-bf16 tensor GEMM (unchanged from R7 — passing) ----------------
#define SMEM_LD 36

template <bool GELU_B, bool GELU_OUT, bool RES>
__global__ __launch_bounds__(256) void mma_gemm(
    const float* __restrict__ A, const float* __restrict__ B, float* __restrict__ C,
    const float* __restrict__ sc, const float* __restrict__ bi,
    const float* __restrict__ res, int M, int Nn, int K)
{
    __shared__ uint16_t Ah[128][SMEM_LD], Al[128][SMEM_LD];
    __shared__ uint16_t Bh[128][SMEM_LD], Bl[128][SMEM_LD];

    const int tid = threadIdx.x;
    const int lane = tid & 31, warp = tid >> 5;
    const int wm = warp >> 2, wn = warp & 3;
    const int m0 = blockIdx.x * 128, n0 = blockIdx.y * 128, z = blockIdx.z;
    const float* Bz = B + (size_t)z * K * Nn;

    float acc[4][4][4];
#pragma unroll
    for (int mi = 0; mi < 4; mi++)
#pragma unroll
        for (int ni = 0; ni < 4; ni++)
#pragma unroll
            for (int q = 0; q < 4; q++) acc[mi][ni][q] = 0.0f;

    float4 pa[4];
    float pb[4][4];
    const int bncol = tid & 127;
    const int bkhalf = (tid >> 7) * 4;
    const int NC = K >> 5;

#pragma unroll
    for (int it = 0; it < 4; it++) {
        int lin = tid + it * 256;
        int row = lin >> 3, c4 = (lin & 7) << 2;
        pa[it] = *reinterpret_cast<const float4*>(&A[(size_t)(m0 + row) * K + c4]);
    }
#pragma unroll
    for (int it = 0; it < 4; it++)
#pragma unroll
        for (int j = 0; j < 4; j++) {
            int k = bkhalf + it * 8 + j;
            pb[it][j] = Bz[(size_t)k * Nn + n0 + bncol];
        }

    for (int kc = 0; kc < NC; kc++) {
#pragma unroll
        for (int it = 0; it < 4; it++) {
            int lin = tid + it * 256;
            int row = lin >> 3, c4 = (lin & 7) << 2;
            float4 v = pa[it];
            uint32_t h0, l0, h1, l1;
            split_pack(v.x, v.y, h0, l0);
            split_pack(v.z, v.w, h1, l1);
            *reinterpret_cast<uint32_t*>(&Ah[row][c4])     = h0;
            *reinterpret_cast<uint32_t*>(&Al[row][c4])     = l0;
            *reinterpret_cast<uint32_t*>(&Ah[row][c4 + 2]) = h1;
            *reinterpret_cast<uint32_t*>(&Al[row][c4 + 2]) = l1;
        }
#pragma unroll
        for (int it = 0; it < 4; it++) {
            float x0 = pb[it][0], x1 = pb[it][1], x2 = pb[it][2], x3 = pb[it][3];
            if (GELU_B) { x0 = gelu_f(x0); x1 = gelu_f(x1); x2 = gelu_f(x2); x3 = gelu_f(x3); }
            uint32_t h0, l0, h1, l1;
            split_pack(x0, x1, h0, l0);
            split_pack(x2, x3, h1, l1);
            int kb = bkhalf + it * 8;
            *reinterpret_cast<uint32_t*>(&Bh[bncol][kb])     = h0;
            *reinterpret_cast<uint32_t*>(&Bl[bncol][kb])     = l0;
            *reinterpret_cast<uint32_t*>(&Bh[bncol][kb + 2]) = h1;
            *reinterpret_cast<uint32_t*>(&Bl[bncol][kb + 2]) = l1;
        }
        __syncthreads();

        if (kc + 1 < NC) {
            int ko = (kc + 1) * 32;
#pragma unroll
            for (int it = 0; it < 4; it++) {
                int lin = tid + it * 256;
                int row = lin >> 3, c4 = (lin & 7) << 2;
                pa[it] = *reinterpret_cast<const float4*>(&A[(size_t)(m0 + row) * K + ko + c4]);
            }
#pragma unroll
            for (int it = 0; it < 4; it++)
#pragma unroll
                for (int j = 0; j < 4; j++) {
                    int k = ko + bkhalf + it * 8 + j;
                    pb[it][j] = Bz[(size_t)k * Nn + n0 + bncol];
                }
        }

#pragma unroll
        for (int ks = 0; ks < 2; ks++) {
            const int kf = ks * 16 + (lane & 3) * 2;
            uint32_t bh[4][2], bl[4][2];
#pragma unroll
            for (int ni = 0; ni < 4; ni++) {
                int n = wn * 32 + ni * 8 + (lane >> 2);
                bh[ni][0] = *reinterpret_cast<const uint32_t*>(&Bh[n][kf]);
                bh[ni][1] = *reinterpret_cast<const uint32_t*>(&Bh[n][kf + 8]);
                bl[ni][0] = *reinterpret_cast<const uint32_t*>(&Bl[n][kf]);
                bl[ni][1] = *reinterpret_cast<const uint32_t*>(&Bl[n][kf + 8]);
            }
#pragma unroll
            for (int mi = 0; mi < 4; mi++) {
                int r = wm * 64 + mi * 16 + (lane >> 2);
                uint32_t ah[4], al[4];
                ah[0] = *reinterpret_cast<const uint32_t*>(&Ah[r][kf]);
                ah[1] = *reinterpret_cast<const uint32_t*>(&Ah[r + 8][kf]);
                ah[2] = *reinterpret_cast<const uint32_t*>(&Ah[r][kf + 8]);
                ah[3] = *reinterpret_cast<const uint32_t*>(&Ah[r + 8][kf + 8]);
                al[0] = *reinterpret_cast<const uint32_t*>(&Al[r][kf]);
                al[1] = *reinterpret_cast<const uint32_t*>(&Al[r + 8][kf]);
                al[2] = *reinterpret_cast<const uint32_t*>(&Al[r][kf + 8]);
                al[3] = *reinterpret_cast<const uint32_t*>(&Al[r + 8][kf + 8]);
#pragma unroll
                for (int ni = 0; ni < 4; ni++) {
                    mma_bf16(acc[mi][ni], ah, bh[ni]);
                    mma_bf16(acc[mi][ni], ah, bl[ni]);
                    mma_bf16(acc[mi][ni], al, bh[ni]);
                }
            }
        }
        __syncthreads();
    }

    float* Cz = C + (size_t)z * M * Nn;
    const float* Rz = RES ? (res + (size_t)z * M * Nn) : nullptr;
#pragma unroll
    for (int mi = 0; mi < 4; mi++) {
        int r0 = m0 + wm * 64 + mi * 16 + (lane >> 2);
        int r1 = r0 + 8;
        float s0 = sc[r0], bb0 = bi[r0];
        float s1 = sc[r1], bb1 = bi[r1];
#pragma unroll
        for (int ni = 0; ni < 4; ni++) {
            int c = n0 + wn * 32 + ni * 8 + (lane & 3) * 2;
            float2 v0, v1;
            v0.x = acc[mi][ni][0] * s0 + bb0;
            v0.y = acc[mi][ni][1] * s0 + bb0;
            v1.x = acc[mi][ni][2] * s1 + bb1;
            v1.y = acc[mi][ni][3] * s1 + bb1;
            if (RES) {
                float2 rr0 = *reinterpret_cast<const float2*>(&Rz[(size_t)r0 * Nn + c]);
                float2 rr1 = *reinterpret_cast<const float2*>(&Rz[(size_t)r1 * Nn + c]);
                v0.x += rr0.x; v0.y += rr0.y;
                v1.x += rr1.x; v1.y += rr1.y;
            }
            if (GELU_OUT) {
                v0.x = gelu_f(v0.x); v0.y = gelu_f(v0.y);
                v1.x = gelu_f(v1.x); v1.y = gelu_f(v1.y);
            }
            *reinterpret_cast<float2*>(&Cz[(size_t)r0 * Nn + c]) = v0;
            *reinterpret_cast<float2*>(&Cz[(size_t)r1 * Nn + c]) = v1;
        }
    }
}

// ---------------- fused flash attention (sim + softmax + ret in one pass) ----------
// grid (64, 2): x = n*8+h, y = l-half (64 query rows). 256 threads = 8 warps (2 wm x 4 wn).
// Per chunk of 128 keys: S = Q^T K (split-bf16 mma), BN, online softmax, O += P V.
// kt layout [key][dk] (18-half stride), vt [dv][key] (136-half stride), qt [l][dk].
static constexpr int KT_LD = 18;
static constexpr int VT_LD = 136;
static constexpr int OFF_KTH = 0;
static constexpr int OFF_KTL = OFF_KTH + 128 * KT_LD * 2;      // 4608
static constexpr int OFF_VTH = OFF_KTL + 128 * KT_LD * 2;      // 9216
static constexpr int OFF_VTL = OFF_VTH + 32 * VT_LD * 2;       // 17920
static constexpr int OFF_QTH = OFF_VTL + 32 * VT_LD * 2;       // 26624
static constexpr int OFF_QTL = OFF_QTH + 64 * KT_LD * 2;       // 28928
static constexpr int OFF_REDA = OFF_QTL + 64 * KT_LD * 2;      // 31232
static constexpr int OFF_REDB = OFF_REDA + 4 * 64 * 4;         // 32256
static constexpr int OFF_LSUM = OFF_REDB + 4 * 64 * 4;         // 33280
static constexpr int OFF_OBUF = OFF_LSUM + 64 * 4;             // 33536
static constexpr int ATTN_SMEM = OFF_OBUF + 4 * 64 * 33 * 4;   // 67328

__global__ __launch_bounds__(256) void fused_attn(
    const float* __restrict__ qkv, const float* __restrict__ pkv,
    const float* __restrict__ s_sim, const float* __restrict__ b_sim,
    const float* __restrict__ s_ret, const float* __restrict__ b_ret,
    float* __restrict__ ret)
{
    extern __shared__ char sm[];
    uint16_t* kth = (uint16_t*)(sm + OFF_KTH);
    uint16_t* ktl = (uint16_t*)(sm + OFF_KTL);
    uint16_t* vth = (uint16_t*)(sm + OFF_VTH);
    uint16_t* vtl = (uint16_t*)(sm + OFF_VTL);
    uint16_t* qth = (uint16_t*)(sm + OFF_QTH);
    uint16_t* qtl = (uint16_t*)(sm + OFF_QTL);
    float* redA = (float*)(sm + OFF_REDA);
    float* redB = (float*)(sm + OFF_REDB);
    float* lsum = (float*)(sm + OFF_LSUM);
    float* obuf = (float*)(sm + OFF_OBUF);

    const int nh = blockIdx.x, n = nh >> 3, h = nh & 7;
    const int lhalf = blockIdx.y;
    const int tid = threadIdx.x, lane = tid & 31, warp = tid >> 5;
    const int wm = warp >> 2, wn = warp & 3;
    const int lg = lane >> 2;      // 0..7
    const int c2 = (lane & 3) * 2; // 0,2,4,6
    const float ss = s_sim[h], sb = b_sim[h];

    // ---- load Q tile: rows l' 0..63 (global l = lhalf*64 + l'), d 0..15 ----
#pragma unroll
    for (int it = 0; it < 4; it++) {
        int idx = tid + it * 256;
        int lq = idx & 63, d = idx >> 6;
        float v = qkv[((size_t)n * 512 + h * 16 + d) * 128 + lhalf * 64 + lq];
        split_u16(v, qth[lq * KT_LD + d], qtl[lq * KT_LD + d]);
    }
    __syncthreads();

    // Q A-frags in registers (reused every chunk)
    uint32_t qa_h[2][4], qa_l[2][4];
#pragma unroll
    for (int mi = 0; mi < 2; mi++) {
        int r = wm * 32 + mi * 16 + lg;
        qa_h[mi][0] = *(const uint32_t*)&qth[r * KT_LD + c2];
        qa_h[mi][1] = *(const uint32_t*)&qth[(r + 8) * KT_LD + c2];
        qa_h[mi][2] = *(const uint32_t*)&qth[r * KT_LD + c2 + 8];
        qa_h[mi][3] = *(const uint32_t*)&qth[(r + 8) * KT_LD + c2 + 8];
        qa_l[mi][0] = *(const uint32_t*)&qtl[r * KT_LD + c2];
        qa_l[mi][1] = *(const uint32_t*)&qtl[(r + 8) * KT_LD + c2];
        qa_l[mi][2] = *(const uint32_t*)&qtl[r * KT_LD + c2 + 8];
        qa_l[mi][3] = *(const uint32_t*)&qtl[(r + 8) * KT_LD + c2 + 8];
    }

    float oacc[2][4][4];
    float m_run[2][2], l_run[2][2];
#pragma unroll
    for (int mi = 0; mi < 2; mi++) {
#pragma unroll
        for (int ni = 0; ni < 4; ni++)
#pragma unroll
            for (int q = 0; q < 4; q++) oacc[mi][ni][q] = 0.0f;
        m_run[mi][0] = m_run[mi][1] = -3.4e38f;
        l_run[mi][0] = l_run[mi][1] = 0.0f;
    }

    for (int c = 0; c < 33; c++) {
        __syncthreads();  // prior chunk's tile reads + redB reads complete
        // ---- load K chunk: kt[mm][d] ----
#pragma unroll
        for (int it = 0; it < 8; it++) {
            int idx = tid + it * 256;
            int mm = idx & 127, d = idx >> 7;
            float v;
            if (c == 0)
                v = qkv[((size_t)n * 512 + 128 + h * 16 + d) * 128 + mm];
            else
                v = pkv[((size_t)n * 384 + h * 16 + d) * 4096 + (c - 1) * 128 + mm];
            split_u16(v, kth[mm * KT_LD + d], ktl[mm * KT_LD + d]);
        }
        // ---- load V chunk transposed: vt[dv][mm] ----
#pragma unroll
        for (int it = 0; it < 16; it++) {
            int idx = tid + it * 256;
            int mm = idx & 127, dv = idx >> 7;
            float v;
            if (c == 0)
                v = qkv[((size_t)n * 512 + 256 + h * 32 + dv) * 128 + mm];
            else
                v = pkv[((size_t)n * 384 + 128 + h * 32 + dv) * 4096 + (c - 1) * 128 + mm];
            split_u16(v, vth[dv * VT_LD + mm], vtl[dv * VT_LD + mm]);
        }
        __syncthreads();

        // ---- S = Q^T K  (sacc[mi][ni][4]) ----
        float sacc[2][4][4];
#pragma unroll
        for (int mi = 0; mi < 2; mi++)
#pragma unroll
            for (int ni = 0; ni < 4; ni++)
#pragma unroll
                for (int q = 0; q < 4; q++) sacc[mi][ni][q] = 0.0f;

        uint32_t kb_h[4][2], kb_l[4][2];
#pragma unroll
        for (int ni = 0; ni < 4; ni++) {
            int nb = wn * 32 + ni * 8 + lg;
            kb_h[ni][0] = *(const uint32_t*)&kth[nb * KT_LD + c2];
            kb_h[ni][1] = *(const uint32_t*)&kth[nb * KT_LD + c2 + 8];
            kb_l[ni][0] = *(const uint32_t*)&ktl[nb * KT_LD + c2];
            kb_l[ni][1] = *(const uint32_t*)&ktl[nb * KT_LD + c2 + 8];
        }
#pragma unroll
        for (int mi = 0; mi < 2; mi++)
#pragma unroll
            for (int ni = 0; ni < 4; ni++) {
                mma_bf16(sacc[mi][ni], qa_h[mi], kb_h[ni]);
                mma_bf16(sacc[mi][ni], qa_h[mi], kb_l[ni]);
                mma_bf16(sacc[mi][ni], qa_l[mi], kb_h[ni]);
            }

        // BN on scores
#pragma unroll
        for (int mi = 0; mi < 2; mi++)
#pragma unroll
            for (int ni = 0; ni < 4; ni++)
#pragma unroll
                for (int q = 0; q < 4; q++) sacc[mi][ni][q] = sacc[mi][ni][q] * ss + sb;

        // ---- chunk row-max (reduce over ni, 4-lane group, then 4 warps) ----
        float cmax[2][2];
#pragma unroll
        for (int mi = 0; mi < 2; mi++)
#pragma unroll
            for (int hf = 0; hf < 2; hf++) {
                float m = fmaxf(sacc[mi][0][hf * 2], sacc[mi][0][hf * 2 + 1]);
#pragma unroll
                for (int ni = 1; ni < 4; ni++)
                    m = fmaxf(m, fmaxf(sacc[mi][ni][hf * 2], sacc[mi][ni][hf * 2 + 1]));
                m = fmaxf(m, __shfl_xor_sync(0xffffffffu, m, 1));
                m = fmaxf(m, __shfl_xor_sync(0xffffffffu, m, 2));
                cmax[mi][hf] = m;
            }
        if ((lane & 3) == 0) {
#pragma unroll
            for (int mi = 0; mi < 2; mi++)
#pragma unroll
                for (int hf = 0; hf < 2; hf++)
                    redA[wn * 64 + wm * 32 + mi * 16 + lg + hf * 8] = cmax[mi][hf];
        }
        __syncthreads();

        float m_new[2][2], f[2][2];
#pragma unroll
        for (int mi = 0; mi < 2; mi++)
#pragma unroll
            for (int hf = 0; hf < 2; hf++) {
                int row = wm * 32 + mi * 16 + lg + hf * 8;
                float m = fmaxf(fmaxf(redA[row], redA[64 + row]),
                                fmaxf(redA[128 + row], redA[192 + row]));
                m = fmaxf(m_run[mi][hf], m);
                f[mi][hf] = __expf(m_run[mi][hf] - m);
                m_new[mi][hf] = m;
            }

        // ---- p = exp(s - m_new), row-sums ----
        float rsum[2][2] = {{0.f, 0.f}, {0.f, 0.f}};
#pragma unroll
        for (int mi = 0; mi < 2; mi++)
#pragma unroll
            for (int ni = 0; ni < 4; ni++) {
                sacc[mi][ni][0] = __expf(sacc[mi][ni][0] - m_new[mi][0]);
                sacc[mi][ni][1] = __expf(sacc[mi][ni][1] - m_new[mi][0]);
                sacc[mi][ni][2] = __expf(sacc[mi][ni][2] - m_new[mi][1]);
                sacc[mi][ni][3] = __expf(sacc[mi][ni][3] - m_new[mi][1]);
                rsum[mi][0] += sacc[mi][ni][0] + sacc[mi][ni][1];
                rsum[mi][1] += sacc[mi][ni][2] + sacc[mi][ni][3];
            }
#pragma unroll
        for (int mi = 0; mi < 2; mi++)
#pragma unroll
            for (int hf = 0; hf < 2; hf++) {
                float s = rsum[mi][hf];
                s += __shfl_xor_sync(0xffffffffu, s, 1);
                s += __shfl_xor_sync(0xffffffffu, s, 2);
                rsum[mi][hf] = s;
            }
        if ((lane & 3) == 0) {
#pragma unroll
            for (int mi = 0; mi < 2; mi++)
#pragma unroll
                for (int hf = 0; hf < 2; hf++)
                    redB[wn * 64 + wm * 32 + mi * 16 + lg + hf * 8] = rsum[mi][hf];
        }
        __syncthreads();
#pragma unroll
        for (int mi = 0; mi < 2; mi++)
#pragma unroll
            for (int hf = 0; hf < 2; hf++) {
                int row = wm * 32 + mi * 16 + lg + hf * 8;
                float tot = redB[row] + redB[64 + row] + redB[128 + row] + redB[192 + row];
                l_run[mi][hf] = l_run[mi][hf] * f[mi][hf] + tot;
                m_run[mi][hf] = m_new[mi][hf];
            }

        // ---- rescale O, then O += P V over this warp's 32 keys ----
#pragma unroll
        for (int mi = 0; mi < 2; mi++)
#pragma unroll
            for (int ni = 0; ni < 4; ni++) {
                oacc[mi][ni][0] *= f[mi][0];
                oacc[mi][ni][1] *= f[mi][0];
                oacc[mi][ni][2] *= f[mi][1];
                oacc[mi][ni][3] *= f[mi][1];
            }
#pragma unroll
        for (int kk = 0; kk < 2; kk++) {
            uint32_t vb_h[4][2], vb_l[4][2];
            int kb = wn * 32 + kk * 16;
#pragma unroll
            for (int no = 0; no < 4; no++) {
                int nb = no * 8 + lg;
                vb_h[no][0] = *(const uint32_t*)&vth[nb * VT_LD + kb + c2];
                vb_h[no][1] = *(const uint32_t*)&vth[nb * VT_LD + kb + c2 + 8];
                vb_l[no][0] = *(const uint32_t*)&vtl[nb * VT_LD + kb + c2];
                vb_l[no][1] = *(const uint32_t*)&vtl[nb * VT_LD + kb + c2 + 8];
            }
#pragma unroll
            for (int mi = 0; mi < 2; mi++) {
                uint32_t pa_h[4], pa_l[4];
                split_pack(sacc[mi][2 * kk][0], sacc[mi][2 * kk][1], pa_h[0], pa_l[0]);
                split_pack(sacc[mi][2 * kk][2], sacc[mi][2 * kk][3], pa_h[1], pa_l[1]);
                split_pack(sacc[mi][2 * kk + 1][0], sacc[mi][2 * kk + 1][1], pa_h[2], pa_l[2]);
                split_pack(sacc[mi][2 * kk + 1][2], sacc[mi][2 * kk + 1][3], pa_h[3], pa_l[3]);
#pragma unroll
                for (int no = 0; no < 4; no++) {
                    mma_bf16(oacc[mi][no], pa_h, vb_h[no]);
                    mma_bf16(oacc[mi][no], pa_h, vb_l[no]);
                    mma_bf16(oacc[mi][no], pa_l, vb_h[no]);
                }
            }
        }
    }

    // ---- write per-warp partial O + row sums; combine; BN+gelu; store ----
    __syncthreads();
#pragma unroll
    for (int mi = 0; mi < 2; mi++)
#pragma unroll
        for (int no = 0; no < 4; no++) {
            int row = wm * 32 + mi * 16 + lg;
            int dv = no * 8 + c2;
            obuf[(wn * 64 + row) * 33 + dv]     = oacc[mi][no][0];
            obuf[(wn * 64 + row) * 33 + dv + 1] = oacc[mi][no][1];
            obuf[(wn * 64 + row + 8) * 33 + dv]     = oacc[mi][no][2];
            obuf[(wn * 64 + row + 8) * 33 + dv + 1] = oacc[mi][no][3];
        }
    if (wn == 0 && (lane & 3) == 0) {
#pragma unroll
        for (int mi = 0; mi < 2; mi++)
#pragma unroll
            for (int hf = 0; hf < 2; hf++)
                lsum[wm * 32 + mi * 16 + lg + hf * 8] = l_run[mi][hf];
    }
    __syncthreads();

#pragma unroll
    for (int it = 0; it < 8; it++) {
        int idx = tid + it * 256;
        int lq = idx & 63, dv = idx >> 6;
        float v = obuf[(0 * 64 + lq) * 33 + dv] + obuf[(1 * 64 + lq) * 33 + dv] +
                  obuf[(2 * 64 + lq) * 33 + dv] + obuf[(3 * 64 + lq) * 33 + dv];
        v = __fdividef(v, lsum[lq]);
        int ch = h * 32 + dv;
        v = v * s_ret[ch] + b_ret[ch];
        ret[((size_t)n * 256 + ch) * 128 + lhalf * 64 + lq] = gelu_f(v);
    }
}

// ---------------- host ----------------
extern "C" void kernel_launch(void* const* d_in, const int* in_sizes, int n_in,
                              void* d_out, int out_size)
{
    (void)in_sizes; (void)n_in; (void)out_size;

    const float* pixel = (const float*)d_in[0];
    const float* query = (const float*)d_in[1];
    const float* w_q1  = (const float*)d_in[2];
    const float* s_q1  = (const float*)d_in[3];
    const float* b_q1  = (const float*)d_in[4];
    const float* w_p1  = (const float*)d_in[5];
    const float* s_p1  = (const float*)d_in[6];
    const float* b_p1  = (const float*)d_in[7];
    const float* w_qkv = (const float*)d_in[8];
    const float* s_qkv = (const float*)d_in[9];
    const float* b_qkv = (const float*)d_in[10];
    const float* w_pkv = (const float*)d_in[11];
    const float* s_pkv = (const float*)d_in[12];
    const float* b_pkv = (const float*)d_in[13];
    const float* s_sim = (const float*)d_in[14];
    const float* b_sim = (const float*)d_in[15];
    const float* s_ret = (const float*)d_in[16];
    const float* b_ret = (const float*)d_in[17];
    const float* w_c3  = (const float*)d_in[18];
    const float* s_c3  = (const float*)d_in[19];
    const float* b_c3  = (const float*)d_in[20];
    const float* w_f1  = (const float*)d_in[21];
    const float* s_f1  = (const float*)d_in[22];
    const float* b_f1  = (const float*)d_in[23];
    const float* w_f2  = (const float*)d_in[24];
    const float* s_f2  = (const float*)d_in[25];
    const float* b_f2  = (const float*)d_in[26];
    float* out = (float*)d_out;

    float *ps, *pkvp, *qs, *qqkv, *retp, *qfp, *ffnp;
    cudaGetSymbolAddress((void**)&ps,   g_pixel_space);
    cudaGetSymbolAddress((void**)&pkvp, g_pixel_kv);
    cudaGetSymbolAddress((void**)&qs,   g_query_space);
    cudaGetSymbolAddress((void**)&qqkv, g_query_qkv);
    cudaGetSymbolAddress((void**)&retp, g_ret);
    cudaGetSymbolAddress((void**)&qfp,  g_qf);
    cudaGetSymbolAddress((void**)&ffnp, g_ffn);

    cudaFuncSetAttribute(fused_attn, cudaFuncAttributeMaxDynamicSharedMemorySize, ATTN_SMEM);

    // 1) pixel_space = gelu(bn(w_p1 @ gelu(pixel)))   M=256 K=2048 N=4096 x8
    mma_gemm<true, true, false><<<dim3(2, 32, 8), 256>>>(
        w_p1, pixel, ps, s_p1, b_p1, nullptr, 256, 4096, 2048);
    // 2) query_space = gelu(bn(w_q1 @ query))         M=256 K=256 N=128 x8
    mma_gemm<false, true, false><<<dim3(2, 1, 8), 256>>>(
        w_q1, query, qs, s_q1, b_q1, nullptr, 256, 128, 256);
    // 3) pixel_kv = bn(w_pkv @ pixel_space)           M=384 K=256 N=4096 x8
    mma_gemm<false, false, false><<<dim3(3, 32, 8), 256>>>(
        w_pkv, ps, pkvp, s_pkv, b_pkv, nullptr, 384, 4096, 256);
    // 4) query_qkv = bn(w_qkv @ query_space)          M=512 K=256 N=128 x8
    mma_gemm<false, false, false><<<dim3(4, 1, 8), 256>>>(
        w_qkv, qs, qqkv, s_qkv, b_qkv, nullptr, 512, 128, 256);
    // 5-7) fused attention: sim + softmax + ret (bn+gelu)
    fused_attn<<<dim3(64, 2), 256, ATTN_SMEM>>>(
        qqkv, pkvp, s_sim, b_sim, s_ret, b_ret, retp);
    // 8) qf = gelu(query + bn(w_c3 @ ret))            M=256 K=256 N=128 x8
    mma_gemm<false, true, true><<<dim3(2, 1, 8), 256>>>(
        w_c3, retp, qfp, s_c3, b_c3, query, 256, 128, 256);
    // 9) ffn = gelu(bn(w_f1 @ qf))                    M=2048 K=256 N=128 x8
    mma_gemm<false, true, false><<<dim3(16, 1, 8), 256>>>(
        w_f1, qfp, ffnp, s_f1, b_f1, nullptr, 2048, 128, 256);
    // 10) out = gelu(qf + bn(w_f2 @ ffn))             M=256 K=2048 N=128 x8
    mma_gemm<false, true, true><<<dim3(2, 1, 8), 256>>>(
        w_f2, ffnp, out, s_f2, b_f2, qfp, 256, 128, 2048);
}